// round 16
// baseline (speedup 1.0000x reference)
#include <cuda_runtime.h>
#include <cuda_bf16.h>
#include <math.h>
#include <stdint.h>

// Problem constants: B=64, Lq=Lk=1024, D=64
#define BDIM   64
#define LDIM   1024
#define DDIM   64
#define TQ     32          // q rows per CTA
#define KT     128         // k/v rows per smem tile
#define NTHR   512
#define KPROW  72          // k/v bf16 plane stride (bf16) -> 144B rows
#define QPROW  72
#define ATROW  136         // attn tile plane stride (bf16) -> 272B rows
#define TENS_SZ (BDIM * LDIM * DDIM)           // 4194304
#define ATT_SZ  ((size_t)BDIM * LDIM * LDIM)   // 67108864

// smem byte layout (108544 B total -> 2 CTAs/SM):
//  [0)      kv stage0: hi 128x72 bf16 (18432) | lo (18432)   -> 36864
//  [36864)  kv stage1: hi | lo                               -> 73728
//           (GEMM2 64KB reduction scratch aliases kv region)
//  [73728)  attn-tile stage0: hi 32x136 (8704) | lo (8704)   -> 91136
//  [91136)  attn-tile stage1: hi | lo                        -> 108544
//           (q planes 9216 B alias the attn-tile region: GEMM1-only lifetime)
#define KVSTAGE 36864
#define OFF_AT  73728
#define ATSTAGE 17408
#define SMEM_BYTES 108544

// global bf16 hi/lo planes (prepass output) + attn planes (main-kernel scratch)
__device__ __nv_bfloat16 g_qhi[TENS_SZ], g_qlo[TENS_SZ];
__device__ __nv_bfloat16 g_khi[TENS_SZ], g_klo[TENS_SZ];
__device__ __nv_bfloat16 g_vhi[TENS_SZ], g_vlo[TENS_SZ];
__device__ __nv_bfloat16 g_ahi[ATT_SZ],  g_alo[ATT_SZ];

__device__ __forceinline__ uint32_t sptr(const void* p) {
    return (uint32_t)__cvta_generic_to_shared(p);
}
__device__ __forceinline__ void bsplit(float x, uint16_t& h, uint16_t& l) {
    __nv_bfloat16 bh = __float2bfloat16(x);
    float r = x - __bfloat162float(bh);
    __nv_bfloat16 bl = __float2bfloat16(r);
    h = __bfloat16_as_ushort(bh);
    l = __bfloat16_as_ushort(bl);
}

#define LDSM_X4(r0,r1,r2,r3, a)                                                  \
    asm volatile("ldmatrix.sync.aligned.m8n8.x4.shared.b16 {%0,%1,%2,%3}, [%4];" \
        : "=r"(r0), "=r"(r1), "=r"(r2), "=r"(r3) : "r"(a))
#define LDSM_X2(r0,r1, a)                                                        \
    asm volatile("ldmatrix.sync.aligned.m8n8.x2.shared.b16 {%0,%1}, [%2];"       \
        : "=r"(r0), "=r"(r1) : "r"(a))
#define LDSM_X2T(r0,r1, a)                                                       \
    asm volatile("ldmatrix.sync.aligned.m8n8.x2.trans.shared.b16 {%0,%1}, [%2];" \
        : "=r"(r0), "=r"(r1) : "r"(a))
#define MMA_BF16(c0,c1,c2,c3, a0,a1,a2,a3, b0,b1)                                \
    asm volatile("mma.sync.aligned.m16n8k16.row.col.f32.bf16.bf16.f32 "          \
        "{%0,%1,%2,%3}, {%4,%5,%6,%7}, {%8,%9}, {%0,%1,%2,%3};"                  \
        : "+f"(c0), "+f"(c1), "+f"(c2), "+f"(c3)                                 \
        : "r"(a0), "r"(a1), "r"(a2), "r"(a3), "r"(b0), "r"(b1))

__device__ __forceinline__ void cpa16(uint32_t dst, const void* src) {
    asm volatile("cp.async.ca.shared.global [%0], [%1], 16;" :: "r"(dst), "l"(src));
}
#define CP_COMMIT() asm volatile("cp.async.commit_group;" ::: "memory")
#define CP_WAIT0()  asm volatile("cp.async.wait_group 0;"  ::: "memory")

// ============================ prepass: fp32 -> bf16 hi/lo planes ============================
__global__ __launch_bounds__(256)
void split_kernel(const float* __restrict__ q,
                  const float* __restrict__ k,
                  const float* __restrict__ v)
{
    const size_t i = ((size_t)blockIdx.x * 256 + threadIdx.x) * 4;
    const int which = blockIdx.y;
    const float* src = (which == 0) ? q : (which == 1) ? k : v;
    __nv_bfloat16* dh = (which == 0) ? g_qhi : (which == 1) ? g_khi : g_vhi;
    __nv_bfloat16* dl = (which == 0) ? g_qlo : (which == 1) ? g_klo : g_vlo;
    const float sc = (which == 0) ? 0.125f : 1.0f;

    float4 f = *(const float4*)(src + i);
    f.x *= sc; f.y *= sc; f.z *= sc; f.w *= sc;
    uint16_t h0,l0,h1,l1,h2,l2,h3,l3;
    bsplit(f.x, h0, l0); bsplit(f.y, h1, l1);
    bsplit(f.z, h2, l2); bsplit(f.w, h3, l3);
    *(uint2*)(dh + i) = make_uint2((uint32_t)h0 | ((uint32_t)h1 << 16),
                                   (uint32_t)h2 | ((uint32_t)h3 << 16));
    *(uint2*)(dl + i) = make_uint2((uint32_t)l0 | ((uint32_t)l1 << 16),
                                   (uint32_t)l2 | ((uint32_t)l3 << 16));
}

// issue one [128 x 64] bf16 hi/lo k/v tile (4 x 16B per thread)
__device__ __forceinline__ void issue_kv_tile(const __nv_bfloat16* __restrict__ ghi,
                                              const __nv_bfloat16* __restrict__ glo,
                                              int tile, uint32_t bhi, uint32_t blo, int tid)
{
    #pragma unroll
    for (int j = 0; j < 2; j++) {
        const int g   = tid + j * 512;
        const int row = g >> 3;
        const int c8  = (g & 7) * 8;
        const size_t off = (size_t)(tile * KT + row) * DDIM + c8;
        const uint32_t d = (uint32_t)((row * KPROW + c8) * 2);
        cpa16(bhi + d, ghi + off);
        cpa16(blo + d, glo + off);
    }
}

// issue one [32 x 128] attn-tile slice from the global attn planes (2 x 16B per thread)
__device__ __forceinline__ void issue_at_tile(const __nv_bfloat16* __restrict__ ghi,
                                              const __nv_bfloat16* __restrict__ glo,
                                              int tile, uint32_t bhi, uint32_t blo, int tid)
{
    const int row = tid >> 4;            // 0..31
    const int c8  = (tid & 15) * 8;      // 0..120
    const size_t off = (size_t)row * LDIM + tile * KT + c8;
    const uint32_t d = (uint32_t)((row * ATROW + c8) * 2);
    cpa16(bhi + d, ghi + off);
    cpa16(blo + d, glo + off);
}

// ============================ main kernel ============================
__global__ __launch_bounds__(NTHR, 2)
void sparse_attn_kernel(const int* __restrict__ maskg,
                        float* __restrict__ outg,
                        float* __restrict__ attng)
{
    extern __shared__ char smem[];
    const uint32_t kb_hi[2] = { sptr(smem),            sptr(smem + KVSTAGE) };
    const uint32_t kb_lo[2] = { sptr(smem + KVSTAGE/2), sptr(smem + KVSTAGE + KVSTAGE/2) };
    const uint32_t ab_hi[2] = { sptr(smem + OFF_AT),           sptr(smem + OFF_AT + ATSTAGE) };
    const uint32_t ab_lo[2] = { sptr(smem + OFF_AT + ATSTAGE/2),
                                sptr(smem + OFF_AT + ATSTAGE + ATSTAGE/2) };
    // q planes alias the attn-tile region (GEMM1-only lifetime)
    uint16_t* q_hi = (uint16_t*)(smem + OFF_AT);
    uint16_t* q_lo = (uint16_t*)(smem + OFF_AT + 4608);

    const int qt   = blockIdx.x;            // 0..31
    const int b    = blockIdx.y;            // 0..63
    const int tid  = threadIdx.x;
    const int w    = tid >> 5;              // warp 0..15
    const int lane = tid & 31;
    const int gr   = lane >> 2;             // 0..7
    const int tg   = lane & 3;              // 0..3

    const int q_row0 = qt * TQ;
    const __nv_bfloat16* qhi_g = g_qhi + ((size_t)b * LDIM + q_row0) * DDIM;
    const __nv_bfloat16* qlo_g = g_qlo + ((size_t)b * LDIM + q_row0) * DDIM;
    const __nv_bfloat16* khi_g = g_khi + (size_t)b * LDIM * DDIM;
    const __nv_bfloat16* klo_g = g_klo + (size_t)b * LDIM * DDIM;
    const __nv_bfloat16* vhi_g = g_vhi + (size_t)b * LDIM * DDIM;
    const __nv_bfloat16* vlo_g = g_vlo + (size_t)b * LDIM * DDIM;
    const __nv_bfloat16* ahi_g = g_ahi + ((size_t)b * LDIM + q_row0) * LDIM;
    const __nv_bfloat16* alo_g = g_alo + ((size_t)b * LDIM + q_row0) * LDIM;
    float* sc_g = attng + ((size_t)b * LDIM + q_row0) * LDIM;   // score scratch = attn out

    // ldmatrix lane addressing
    const int g4      = lane >> 3;
    const int arow    = (lane & 7) | ((g4 & 1) << 3);   // A row within 16
    const int acolofs = (g4 >> 1) << 3;                 // A +0/+8 k-offset
    const int li      = lane & 15;
    const int brow8   = li & 7;
    const int bmat    = li >> 3;

    // ---- prologue: cp.async q planes + k tile 0 (one group) ----
    {
        const int pl  = tid >> 8;           // 0=hi 1=lo
        const int g   = tid & 255;
        const int row = g >> 3;
        const int c8  = (g & 7) * 8;
        const size_t off = (size_t)row * DDIM + c8;
        const __nv_bfloat16* src = (pl ? qlo_g : qhi_g) + off;
        const uint32_t dst = (pl ? sptr(q_lo) : sptr(q_hi)) + (uint32_t)((row * QPROW + c8) * 2);
        cpa16(dst, src);
    }
    issue_kv_tile(khi_g, klo_g, 0, kb_hi[0], kb_lo[0], tid);
    CP_COMMIT();
    CP_WAIT0();
    __syncthreads();

    // ---- hoist q fragments into registers (32 regs, GEMM1 lifetime) ----
    const uint32_t qhi_b = sptr(q_hi), qlo_b = sptr(q_lo);
    uint32_t qa_h[2][4][4], qa_l[2][4][4];
    #pragma unroll
    for (int rg = 0; rg < 2; rg++)
        #pragma unroll
        for (int kc = 0; kc < 4; kc++) {
            const uint32_t ao =
                (uint32_t)((rg * 16 + arow) * QPROW + kc * 16 + acolofs) * 2;
            LDSM_X4(qa_h[rg][kc][0], qa_h[rg][kc][1], qa_h[rg][kc][2], qa_h[rg][kc][3],
                    qhi_b + ao);
            LDSM_X4(qa_l[rg][kc][0], qa_l[rg][kc][1], qa_l[rg][kc][2], qa_l[rg][kc][3],
                    qlo_b + ao);
        }

    // ==================== GEMM1: scores -> global (attng as scratch) ====================
    const int nb = 8 * w;
    for (int t = 0; t < LDIM / KT; t++) {
        CP_WAIT0();
        __syncthreads();
        if (t < LDIM / KT - 1) {
            issue_kv_tile(khi_g, klo_g, t + 1, kb_hi[(t+1)&1], kb_lo[(t+1)&1], tid);
            CP_COMMIT();
        }

        const uint32_t khi_b = kb_hi[t & 1];
        const uint32_t klo_b = kb_lo[t & 1];
        float c0[2] = {0.f,0.f}, c1[2] = {0.f,0.f}, c2[2] = {0.f,0.f}, c3[2] = {0.f,0.f};
        #pragma unroll
        for (int kc = 0; kc < 4; kc++) {
            uint32_t bh0,bh1, bl0,bl1;
            const uint32_t bofs = (uint32_t)((nb + brow8) * KPROW + kc * 16 + bmat * 8) * 2;
            LDSM_X2(bh0,bh1, khi_b + bofs);
            LDSM_X2(bl0,bl1, klo_b + bofs);
            #pragma unroll
            for (int rg = 0; rg < 2; rg++) {
                MMA_BF16(c0[rg],c1[rg],c2[rg],c3[rg],
                         qa_h[rg][kc][0],qa_h[rg][kc][1],qa_h[rg][kc][2],qa_h[rg][kc][3],
                         bl0,bl1);
                MMA_BF16(c0[rg],c1[rg],c2[rg],c3[rg],
                         qa_l[rg][kc][0],qa_l[rg][kc][1],qa_l[rg][kc][2],qa_l[rg][kc][3],
                         bh0,bh1);
                MMA_BF16(c0[rg],c1[rg],c2[rg],c3[rg],
                         qa_h[rg][kc][0],qa_h[rg][kc][1],qa_h[rg][kc][2],qa_h[rg][kc][3],
                         bh0,bh1);
            }
        }
        #pragma unroll
        for (int rg = 0; rg < 2; rg++) {
            float* sp = sc_g + (size_t)(rg * 16 + gr) * LDIM + t * KT + nb + 2 * tg;
            *(float2*)sp              = make_float2(c0[rg], c1[rg]);
            *(float2*)(sp + 8 * LDIM) = make_float2(c2[rg], c3[rg]);
        }
    }

    // prefetch v tile 0 (latency hides behind sparsemax)
    issue_kv_tile(vhi_g, vlo_g, 0, kb_hi[0], kb_lo[0], tid);
    CP_COMMIT();
    __syncthreads();   // score writes visible block-wide

    // ============ mask + sparsemax (Michelot; one row at a time, 2 rows/warp) ============
    #pragma unroll
    for (int rr = 0; rr < 2; rr++) {
        const int row  = w * 2 + rr;
        const int grow = q_row0 + row;
        float z[32];
        {
            const float* srow = sc_g + (size_t)row * LDIM;
            const int4* m4 = (const int4*)(maskg + ((size_t)b * LDIM + grow) * LDIM);
            #pragma unroll
            for (int jj = 0; jj < 8; jj++) {
                int col = lane * 4 + 128 * jj;
                int4   mb = m4[col >> 2];
                float4 s  = *(const float4*)(srow + col);
                z[jj*4+0] = mb.x ? -INFINITY : s.x;
                z[jj*4+1] = mb.y ? -INFINITY : s.y;
                z[jj*4+2] = mb.z ? -INFINITY : s.z;
                z[jj*4+3] = mb.w ? -INFINITY : s.w;
            }
        }
        float s = 0.0f; int c = 0;
        #pragma unroll
        for (int i = 0; i < 32; i++)
            if (z[i] > -INFINITY) { s += z[i]; c++; }
        #pragma unroll
        for (int o = 16; o >= 1; o >>= 1) {
            s += __shfl_xor_sync(0xffffffffu, s, o);
            c += __shfl_xor_sync(0xffffffffu, c, o);
        }
        float tau = (c > 0) ? (s - 1.0f) / (float)c : INFINITY;
        int prev = c;
        for (int it = 0; it < 64; it++) {
            float s2 = 0.0f; int c2 = 0;
            #pragma unroll
            for (int i = 0; i < 32; i++)
                if (z[i] > tau) { s2 += z[i]; c2++; }
            #pragma unroll
            for (int o = 16; o >= 1; o >>= 1) {
                s2 += __shfl_xor_sync(0xffffffffu, s2, o);
                c2 += __shfl_xor_sync(0xffffffffu, c2, o);
            }
            bool done = (c2 == prev) || (c2 == 0);
            prev = c2;
            if (c2 > 0) tau = (s2 - 1.0f) / (float)c2;
            if (done) break;   // warp-uniform after shuffle reduction
        }
        // emit: attn fp32 -> attng (overwrites scores); bf16 hi/lo -> global planes
        {
            float* arow_g = sc_g + (size_t)row * LDIM;
            __nv_bfloat16* phi = (__nv_bfloat16*)(ahi_g + (size_t)row * LDIM);
            __nv_bfloat16* plo = (__nv_bfloat16*)(alo_g + (size_t)row * LDIM);
            #pragma unroll
            for (int jj = 0; jj < 8; jj++) {
                int col = lane * 4 + 128 * jj;
                float a0 = fmaxf(z[jj*4+0] - tau, 0.0f);
                float a1 = fmaxf(z[jj*4+1] - tau, 0.0f);
                float a2 = fmaxf(z[jj*4+2] - tau, 0.0f);
                float a3 = fmaxf(z[jj*4+3] - tau, 0.0f);
                *(float4*)(arow_g + col) = make_float4(a0, a1, a2, a3);
                uint16_t h0,l0,h1,l1,h2,l2,h3,l3;
                bsplit(a0,h0,l0); bsplit(a1,h1,l1); bsplit(a2,h2,l2); bsplit(a3,h3,l3);
                *(uint2*)(phi + col) = make_uint2((uint32_t)h0 | ((uint32_t)h1<<16),
                                                  (uint32_t)h2 | ((uint32_t)h3<<16));
                *(uint2*)(plo + col) = make_uint2((uint32_t)l0 | ((uint32_t)l1<<16),
                                                  (uint32_t)l2 | ((uint32_t)l3<<16));
            }
        }
    }
    __syncthreads();   // attn plane writes visible before cp.async reads them
    issue_at_tile(ahi_g, alo_g, 0, ab_hi[0], ab_lo[0], tid);
    CP_COMMIT();

    // ==================== GEMM2: out = attn . v  (bf16x3, dual cp.async streams) ====================
    const int ksw = w & 7;
    const int nh  = w >> 3;
    float d0[2][4], d1[2][4], d2[2][4], d3[2][4];
    #pragma unroll
    for (int rg = 0; rg < 2; rg++)
        #pragma unroll
        for (int nt = 0; nt < 4; nt++) { d0[rg][nt]=d1[rg][nt]=d2[rg][nt]=d3[rg][nt]=0.f; }

    for (int t = 0; t < LDIM / KT; t++) {
        CP_WAIT0();        // v tile t + attn tile t arrived
        __syncthreads();
        if (t < LDIM / KT - 1) {
            issue_kv_tile(vhi_g, vlo_g, t + 1, kb_hi[(t+1)&1], kb_lo[(t+1)&1], tid);
            issue_at_tile(ahi_g, alo_g, t + 1, ab_hi[(t+1)&1], ab_lo[(t+1)&1], tid);
            CP_COMMIT();
        }

        const uint32_t vhi_b = kb_hi[t & 1];
        const uint32_t vlo_b = kb_lo[t & 1];
        const uint32_t athi_b = ab_hi[t & 1];
        const uint32_t atlo_b = ab_lo[t & 1];

        #pragma unroll
        for (int rg = 0; rg < 2; rg++) {
            uint32_t ah0,ah1,ah2,ah3, al0,al1,al2,al3;
            const uint32_t ao =
                (uint32_t)((rg * 16 + arow) * ATROW + 16 * ksw + acolofs) * 2;
            LDSM_X4(ah0,ah1,ah2,ah3, athi_b + ao);
            LDSM_X4(al0,al1,al2,al3, atlo_b + ao);
            #pragma unroll
            for (int nt = 0; nt < 4; nt++) {
                const uint32_t bofs =
                    (uint32_t)((16 * ksw + brow8 + bmat * 8) * KPROW + nh * 32 + nt * 8) * 2;
                uint32_t bh0,bh1, bl0,bl1;
                LDSM_X2T(bh0,bh1, vhi_b + bofs);
                LDSM_X2T(bl0,bl1, vlo_b + bofs);
                MMA_BF16(d0[rg][nt],d1[rg][nt],d2[rg][nt],d3[rg][nt],
                         ah0,ah1,ah2,ah3, bl0,bl1);
                MMA_BF16(d0[rg][nt],d1[rg][nt],d2[rg][nt],d3[rg][nt],
                         al0,al1,al2,al3, bh0,bh1);
                MMA_BF16(d0[rg][nt],d1[rg][nt],d2[rg][nt],d3[rg][nt],
                         ah0,ah1,ah2,ah3, bh0,bh1);
            }
        }
    }
    __syncthreads();   // all plane reads done -> reduction may overwrite kv region

    // cross-warp reduction: 8 k-slice partials per n-half, via kv region
    float* red = (float*)smem;   // 16 warps * 32 rows * 32 cols fp32 = 64KB
    #pragma unroll
    for (int rg = 0; rg < 2; rg++)
        #pragma unroll
        for (int nt = 0; nt < 4; nt++) {
            const int nl = nt * 8 + 2 * tg;
            float* rp = red + w * 1024 + (rg * 16 + gr) * 32 + nl;
            *(float2*)rp            = make_float2(d0[rg][nt], d1[rg][nt]);
            *(float2*)(rp + 8 * 32) = make_float2(d2[rg][nt], d3[rg][nt]);
        }
    __syncthreads();
    {
        const int o  = tid * 4;          // 0..2044
        const int m  = o >> 6;           // 0..31
        const int n  = o & 63;
        const int wb = (n >> 5) * 8;
        const int nl = n & 31;
        float4 sum = make_float4(0.f, 0.f, 0.f, 0.f);
        #pragma unroll
        for (int j = 0; j < 8; j++) {
            float4 p = *(float4*)(red + (wb + j) * 1024 + m * 32 + nl);
            sum.x += p.x; sum.y += p.y; sum.z += p.z; sum.w += p.w;
        }
        *(float4*)(outg + ((size_t)b * LDIM + q_row0 + m) * DDIM + n) = sum;
    }
}

extern "C" void kernel_launch(void* const* d_in, const int* in_sizes, int n_in,
                              void* d_out, int out_size)
{
    const float* q    = (const float*)d_in[0];
    const float* k    = (const float*)d_in[1];
    const float* v    = (const float*)d_in[2];
    const int*   mask = (const int*)d_in[3];

    float* out  = (float*)d_out;                                // [B, Lq, D]
    float* attn = (float*)d_out + (size_t)BDIM * LDIM * DDIM;   // [B, Lq, Lk]

    // prepass: fp32 -> bf16 hi/lo planes
    dim3 pgrid(TENS_SZ / (256 * 4), 3);
    split_kernel<<<pgrid, 256>>>(q, k, v);

    cudaFuncSetAttribute(sparse_attn_kernel,
                         cudaFuncAttributeMaxDynamicSharedMemorySize,
                         SMEM_BYTES);
    dim3 grid(LDIM / TQ, BDIM);   // (32, 64)
    dim3 block(NTHR);
    sparse_attn_kernel<<<grid, block, SMEM_BYTES>>>(mask, out, attn);
}